// round 11
// baseline (speedup 1.0000x reference)
#include <cuda_runtime.h>
#include <cuda_fp16.h>
#include <mma.h>
#include <cstdint>

using namespace nvcuda;

#define N_NODES 50000
#define E_EDGES 800000
#define F 128
#define CAP 64             // max edges/dst (deg~Poisson(16); P(deg>64) ~ 1e-20)

// __device__ scratch (allocation-free rule)
__device__ __align__(16) __half g_hidden[(size_t)N_NODES * F];  // 12.8 MB
__device__ __align__(16) int  g_cnt[N_NODES + 12];              // padded for int4 zeroing
__device__ __align__(16) int2 g_slot[(size_t)N_NODES * CAP];    // 25.6 MB

#define BM 64
#define GEMM_BLOCKS ((N_NODES + BM - 1) / BM)              // 782
#define FILL_BLOCKS ((E_EDGES + 255) / 256)                // 3125
#define TOTAL_BLOCKS (GEMM_BLOCKS + FILL_BLOCKS)           // 3907

// ---------------------------------------------------------------------------
// Kernel A: zero per-dst counters (int4 stores)
// ---------------------------------------------------------------------------
__global__ void zero_cnt_kernel(int* __restrict__ cnt) {
    int i = blockIdx.x * blockDim.x + threadIdx.x;
    if (i < (N_NODES + 3) / 4)
        ((int4*)cnt)[i] = make_int4(0, 0, 0, 0);
}

// ---------------------------------------------------------------------------
// GEMM body: hidden[m][n] = sum_k x[m][k]*W[n][k] + b[n]  (fp16 out, HMMA)
// 64x128 output tile per block, processed in TWO 64-col N-halves so smem is
// only 32KB (xs 16KB persistent + wsm 16KB per-half; epilogue staged into the
// wsm region).  8 warps in 4x2 grid; each warp 16x32 via 1x2 wmma frags.
// ---------------------------------------------------------------------------
__device__ __forceinline__ void gemm_body(
    const float* __restrict__ x,
    const float* __restrict__ W,
    const float* __restrict__ b,
    __half* __restrict__ hidden,
    unsigned char* smem_raw,
    int gemm_id)
{
    __half* xs  = (__half*)smem_raw;            // [64][128] fp16, 16KB
    __half* wsm = xs + 64 * 128;                // [64][128] fp16, 16KB (per half)
    float*  out_s = (float*)wsm;                // [64][64] fp32, 16KB (epilogue reuse)

    const int tid = threadIdx.x;
    const int block_row = gemm_id * BM;
    const int wid = tid >> 5;
    const int warp_m = wid >> 1;                // 0..3: rows warp_m*16
    const int warp_n = wid & 1;                 // 0..1: cols warp_n*32

    // ---- x tile fp32->fp16 (once): 64x128 = 2048 float4, 8/thread ----
#pragma unroll
    for (int i = 0; i < 8; i++) {
        const int idx = tid + i * 256;
        const int r = idx >> 5;
        const int c4 = idx & 31;
        const int grow = block_row + r;
        float4 v = make_float4(0.f, 0.f, 0.f, 0.f);
        if (grow < N_NODES)
            v = *(const float4*)&x[(size_t)grow * F + c4 * 4];
        *(__half2*)&xs[r * 128 + c4 * 4]     = __floats2half2_rn(v.x, v.y);
        *(__half2*)&xs[r * 128 + c4 * 4 + 2] = __floats2half2_rn(v.z, v.w);
    }

#pragma unroll
    for (int half = 0; half < 2; half++) {
        const int n0 = half * 64;

        // ---- W[n0 .. n0+63][:] fp32->fp16: 64x128 = 2048 float4, 8/thread ----
        __syncthreads();   // (half 0: pairs with xs loads; half 1: out_s reads done)
#pragma unroll
        for (int i = 0; i < 8; i++) {
            const int idx = tid + i * 256;
            const int r = idx >> 5;              // local W row 0..63
            const int c4 = idx & 31;
            float4 v = *(const float4*)&W[(size_t)(n0 + r) * F + c4 * 4];
            *(__half2*)&wsm[r * 128 + c4 * 4]     = __floats2half2_rn(v.x, v.y);
            *(__half2*)&wsm[r * 128 + c4 * 4 + 2] = __floats2half2_rn(v.z, v.w);
        }
        __syncthreads();

        wmma::fragment<wmma::accumulator, 16, 16, 16, float> acc[2];
        wmma::fill_fragment(acc[0], 0.f);
        wmma::fill_fragment(acc[1], 0.f);

#pragma unroll
        for (int k0 = 0; k0 < F; k0 += 16) {
            wmma::fragment<wmma::matrix_a, 16, 16, 16, __half, wmma::row_major> a;
            wmma::fragment<wmma::matrix_b, 16, 16, 16, __half, wmma::col_major> bf[2];
            wmma::load_matrix_sync(a, &xs[(warp_m * 16) * 128 + k0], 128);
#pragma unroll
            for (int jn = 0; jn < 2; jn++)
                wmma::load_matrix_sync(bf[jn], &wsm[(warp_n * 32 + jn * 16) * 128 + k0], 128);
            wmma::mma_sync(acc[0], a, bf[0], acc[0]);
            wmma::mma_sync(acc[1], a, bf[1], acc[1]);
        }

        __syncthreads();   // wsm reads done; safe to overwrite as out_s
#pragma unroll
        for (int jn = 0; jn < 2; jn++)
            wmma::store_matrix_sync(
                &out_s[(warp_m * 16) * 64 + warp_n * 32 + jn * 16],
                acc[jn], 64, wmma::mem_row_major);
        __syncthreads();

        // ---- epilogue: 64x64 fp32 -> bias+fp16, 1024 float4, 4/thread ----
#pragma unroll
        for (int i = 0; i < 4; i++) {
            const int idx = tid + i * 256;       // 0..1023
            const int r = idx >> 4;              // row 0..63
            const int c4 = idx & 15;             // col group within half
            const int grow = block_row + r;
            if (grow < N_NODES) {
                float4 v = *(const float4*)&out_s[r * 64 + c4 * 4];
                const float4 bias = *(const float4*)&b[n0 + c4 * 4];
                union { uint2 u; __half2 h[2]; } pk;
                pk.h[0] = __floats2half2_rn(v.x + bias.x, v.y + bias.y);
                pk.h[1] = __floats2half2_rn(v.z + bias.z, v.w + bias.w);
                *(uint2*)&hidden[(size_t)grow * F + n0 + c4 * 4] = pk.u;
            }
        }
    }
}

// ---------------------------------------------------------------------------
// Fill body: bucket edges by dst.  edge_index int32 [2,E]: row0=dst, row1=src.
// ---------------------------------------------------------------------------
__device__ __forceinline__ void fill_body(
    const int* __restrict__ edge_index,
    const float* __restrict__ edge_weight,
    int* __restrict__ cnt,
    int2* __restrict__ slot,
    int fill_id)
{
    const int e = fill_id * 256 + threadIdx.x;
    if (e >= E_EDGES) return;
    const int dst = edge_index[e];
    const int src = edge_index[E_EDGES + e];
    const float w = edge_weight[e];
    const int pos = atomicAdd(&cnt[dst], 1);
    if (pos < CAP)
        slot[(size_t)dst * CAP + pos] = make_int2(src, __float_as_int(w));
}

// ---------------------------------------------------------------------------
// Fused kernel: range split, 32KB static smem (7 blocks/SM for BOTH roles).
// ---------------------------------------------------------------------------
__global__ __launch_bounds__(256) void gemm_fill_fused_kernel(
    const float* __restrict__ x,
    const float* __restrict__ W,
    const float* __restrict__ b,
    const int* __restrict__ edge_index,
    const float* __restrict__ edge_weight,
    __half* __restrict__ hidden,
    int* __restrict__ cnt,
    int2* __restrict__ slot)
{
    __shared__ __align__(16) unsigned char smem_raw[32 * 1024];
    const int bid = blockIdx.x;
    if (bid < GEMM_BLOCKS) {
        gemm_body(x, W, b, hidden, smem_raw, bid);
    } else {
        fill_body(edge_index, edge_weight, cnt, slot, bid - GEMM_BLOCKS);
    }
}

// ---------------------------------------------------------------------------
// Gather SpMM — EXACT R6/R8 structure (proven 34.6us, three bench runs).
// One warp per dst node; lane l owns feats 4l..4l+3 (8 fp16 bytes).
// fp32 accumulation, unroll x2, int2 slot loads, all-const params, no reset.
// DO NOT unroll further: x4 regressed in R7 (88.7us) and R9 (isolated).
// ---------------------------------------------------------------------------
__global__ __launch_bounds__(256) void spmm_gather_kernel(
    const int* __restrict__ cnt_arr,
    const int2* __restrict__ slot,
    const __half* __restrict__ hidden,
    float* __restrict__ out)
{
    const int node = blockIdx.x * (blockDim.x >> 5) + (threadIdx.x >> 5);
    const int lane = threadIdx.x & 31;
    if (node >= N_NODES) return;

    int cnt = cnt_arr[node];
    if (cnt > CAP) cnt = CAP;
    const int2* __restrict__ sl = &slot[(size_t)node * CAP];

    float4 acc = make_float4(0.f, 0.f, 0.f, 0.f);

    int j = 0;
    for (; j + 2 <= cnt; j += 2) {
        const int2 e0 = sl[j];
        const int2 e1 = sl[j + 1];
        const uint2 r0 = *(const uint2*)&hidden[(size_t)e0.x * F + lane * 4];
        const uint2 r1 = *(const uint2*)&hidden[(size_t)e1.x * F + lane * 4];
        const float w0 = __int_as_float(e0.y);
        const float w1 = __int_as_float(e1.y);
        float2 a01 = __half22float2(*(const __half2*)&r0.x);
        float2 a23 = __half22float2(*(const __half2*)&r0.y);
        float2 b01 = __half22float2(*(const __half2*)&r1.x);
        float2 b23 = __half22float2(*(const __half2*)&r1.y);
        acc.x += w0 * a01.x + w1 * b01.x;
        acc.y += w0 * a01.y + w1 * b01.y;
        acc.z += w0 * a23.x + w1 * b23.x;
        acc.w += w0 * a23.y + w1 * b23.y;
    }
    if (j < cnt) {
        const int2 e0 = sl[j];
        const uint2 r0 = *(const uint2*)&hidden[(size_t)e0.x * F + lane * 4];
        const float w0 = __int_as_float(e0.y);
        float2 a01 = __half22float2(*(const __half2*)&r0.x);
        float2 a23 = __half22float2(*(const __half2*)&r0.y);
        acc.x += w0 * a01.x;
        acc.y += w0 * a01.y;
        acc.z += w0 * a23.x;
        acc.w += w0 * a23.y;
    }
    *(float4*)&out[(size_t)node * F + lane * 4] = acc;
}

// ---------------------------------------------------------------------------
// Launch
// Inputs: x [N,128] f32, edge_index [2,E] i32, edge_weight [E] f32,
//         W [128,128] f32, b [128] f32.  Output: [N,128] f32.
// ---------------------------------------------------------------------------
extern "C" void kernel_launch(void* const* d_in, const int* in_sizes, int n_in,
                              void* d_out, int out_size) {
    const float* x  = (const float*)d_in[0];
    const int*   ei = (const int*)d_in[1];
    const float* ew = (const float*)d_in[2];
    const float* W  = (const float*)d_in[3];
    const float* b  = (const float*)d_in[4];
    float* out = (float*)d_out;

    __half* hidden; int* cnt; int2* slot;
    cudaGetSymbolAddress((void**)&hidden, g_hidden);
    cudaGetSymbolAddress((void**)&cnt, g_cnt);
    cudaGetSymbolAddress((void**)&slot, g_slot);

    // A) zero per-dst counters
    {
        const int n4 = (N_NODES + 3) / 4;
        zero_cnt_kernel<<<(n4 + 255) / 256, 256>>>(cnt);
    }
    // B) HMMA GEMM (fp16 hidden, 32KB smem) overlapped with edge bucketing
    gemm_fill_fused_kernel<<<TOTAL_BLOCKS, 256>>>(x, W, b, ei, ew, hidden, cnt, slot);

    // C) out[dst] = sum w * hidden[src]  (gather; writes all rows)
    {
        const int warps_per_block = 256 / 32;
        const int grid = (N_NODES + warps_per_block - 1) / warps_per_block;
        spmm_gather_kernel<<<grid, 256>>>(cnt, slot, hidden, out);
    }
}

// round 12
// speedup vs baseline: 1.2879x; 1.2879x over previous
#include <cuda_runtime.h>
#include <cuda_fp16.h>
#include <mma.h>
#include <cstdint>

using namespace nvcuda;

#define N_NODES 50000
#define E_EDGES 800000
#define F 128
#define CAP 64             // max edges/dst (deg~Poisson(16); P(deg>64) ~ 1e-20)

// __device__ scratch (allocation-free rule)
__device__ __align__(16) __half g_hidden[(size_t)N_NODES * F];  // 12.8 MB
__device__ __align__(16) int  g_cnt[N_NODES + 12];              // padded for int4 zeroing
__device__ __align__(16) int2 g_slot[(size_t)N_NODES * CAP];    // 25.6 MB

#define BM 64
#define GEMM_BLOCKS ((N_NODES + BM - 1) / BM)              // 782
#define FILL_BLOCKS ((E_EDGES + 255) / 256)                // 3125
#define TOTAL_BLOCKS (GEMM_BLOCKS + FILL_BLOCKS)           // 3907

// ---------------------------------------------------------------------------
// Kernel A: zero per-dst counters (int4 stores)
// ---------------------------------------------------------------------------
__global__ void zero_cnt_kernel(int* __restrict__ cnt) {
    int i = blockIdx.x * blockDim.x + threadIdx.x;
    if (i < (N_NODES + 3) / 4)
        ((int4*)cnt)[i] = make_int4(0, 0, 0, 0);
}

// ---------------------------------------------------------------------------
// GEMM body — EXACT R8 structure (proven ~36us fused).  64x128 tile, full
// K=128 in smem (48KB).  8 warps (2x4), each 32x32 via 2x2 wmma frags.
// DO NOT restructure to 32KB/two-half form: costs +16us (R9/R10 measured).
// ---------------------------------------------------------------------------
__device__ __forceinline__ void gemm_body(
    const float* __restrict__ x,
    const float* __restrict__ W,
    const float* __restrict__ b,
    __half* __restrict__ hidden,
    unsigned char* smem_raw,
    int gemm_id)
{
    __half* xs  = (__half*)smem_raw;            // [64][128]
    __half* wsm = xs + 64 * 128;                // [128][128]
    float*  out_s = (float*)smem_raw;           // [64][128] (epilogue reuse)

    const int tid = threadIdx.x;
    const int block_row = gemm_id * BM;

    // ---- x tile fp32->fp16: 64x128 = 2048 float4, 8/thread ----
#pragma unroll
    for (int i = 0; i < 8; i++) {
        const int idx = tid + i * 256;
        const int r = idx >> 5;
        const int c4 = idx & 31;
        const int grow = block_row + r;
        float4 v = make_float4(0.f, 0.f, 0.f, 0.f);
        if (grow < N_NODES)
            v = *(const float4*)&x[(size_t)grow * F + c4 * 4];
        *(__half2*)&xs[r * 128 + c4 * 4]     = __floats2half2_rn(v.x, v.y);
        *(__half2*)&xs[r * 128 + c4 * 4 + 2] = __floats2half2_rn(v.z, v.w);
    }
    // ---- W fp32->fp16: 128x128 = 4096 float4, 16/thread ----
#pragma unroll
    for (int i = 0; i < 16; i++) {
        const int idx = tid + i * 256;
        const int n = idx >> 5;
        const int c4 = idx & 31;
        float4 v = *(const float4*)&W[(size_t)n * F + c4 * 4];
        *(__half2*)&wsm[n * 128 + c4 * 4]     = __floats2half2_rn(v.x, v.y);
        *(__half2*)&wsm[n * 128 + c4 * 4 + 2] = __floats2half2_rn(v.z, v.w);
    }
    __syncthreads();

    const int wid = tid >> 5;
    const int warp_m = wid & 1;
    const int warp_n = wid >> 1;

    wmma::fragment<wmma::accumulator, 16, 16, 16, float> acc[2][2];
#pragma unroll
    for (int im = 0; im < 2; im++)
#pragma unroll
        for (int jn = 0; jn < 2; jn++)
            wmma::fill_fragment(acc[im][jn], 0.f);

#pragma unroll
    for (int k0 = 0; k0 < F; k0 += 16) {
        wmma::fragment<wmma::matrix_a, 16, 16, 16, __half, wmma::row_major> a[2];
        wmma::fragment<wmma::matrix_b, 16, 16, 16, __half, wmma::col_major> bf[2];
#pragma unroll
        for (int im = 0; im < 2; im++)
            wmma::load_matrix_sync(a[im], &xs[(warp_m * 32 + im * 16) * 128 + k0], 128);
#pragma unroll
        for (int jn = 0; jn < 2; jn++)
            wmma::load_matrix_sync(bf[jn], &wsm[(warp_n * 32 + jn * 16) * 128 + k0], 128);
#pragma unroll
        for (int im = 0; im < 2; im++)
#pragma unroll
            for (int jn = 0; jn < 2; jn++)
                wmma::mma_sync(acc[im][jn], a[im], bf[jn], acc[im][jn]);
    }

    __syncthreads();
#pragma unroll
    for (int im = 0; im < 2; im++)
#pragma unroll
        for (int jn = 0; jn < 2; jn++)
            wmma::store_matrix_sync(
                &out_s[(warp_m * 32 + im * 16) * 128 + warp_n * 32 + jn * 16],
                acc[im][jn], 128, wmma::mem_row_major);
    __syncthreads();

#pragma unroll
    for (int i = 0; i < 8; i++) {
        const int idx = tid + i * 256;
        const int r = idx >> 5;
        const int c4 = idx & 31;
        const int grow = block_row + r;
        if (grow < N_NODES) {
            float4 v = *(const float4*)&out_s[r * 128 + c4 * 4];
            const float4 bias = *(const float4*)&b[c4 * 4];
            union { uint2 u; __half2 h[2]; } pk;
            pk.h[0] = __floats2half2_rn(v.x + bias.x, v.y + bias.y);
            pk.h[1] = __floats2half2_rn(v.z + bias.z, v.w + bias.w);
            *(uint2*)&hidden[(size_t)grow * F + c4 * 4] = pk.u;
        }
    }
}

// ---------------------------------------------------------------------------
// Fill body: bucket edges by dst.  edge_index int32 [2,E]: row0=dst, row1=src.
// ---------------------------------------------------------------------------
__device__ __forceinline__ void fill_body(
    const int* __restrict__ edge_index,
    const float* __restrict__ edge_weight,
    int* __restrict__ cnt,
    int2* __restrict__ slot,
    int fill_id)
{
    const int e = fill_id * 256 + threadIdx.x;
    if (e >= E_EDGES) return;
    const int dst = edge_index[e];
    const int src = edge_index[E_EDGES + e];
    const float w = edge_weight[e];
    const int pos = atomicAdd(&cnt[dst], 1);
    if (pos < CAP)
        slot[(size_t)dst * CAP + pos] = make_int2(src, __float_as_int(w));
}

// ---------------------------------------------------------------------------
// Fused kernel: range split, 48KB static smem (EXACT R8 config, proven).
// ---------------------------------------------------------------------------
__global__ __launch_bounds__(256) void gemm_fill_fused_kernel(
    const float* __restrict__ x,
    const float* __restrict__ W,
    const float* __restrict__ b,
    const int* __restrict__ edge_index,
    const float* __restrict__ edge_weight,
    __half* __restrict__ hidden,
    int* __restrict__ cnt,
    int2* __restrict__ slot)
{
    __shared__ __align__(16) unsigned char smem_raw[48 * 1024];
    const int bid = blockIdx.x;
    if (bid < GEMM_BLOCKS) {
        gemm_body(x, W, b, hidden, smem_raw, bid);
    } else {
        fill_body(edge_index, edge_weight, cnt, slot, bid - GEMM_BLOCKS);
    }
}

// ---------------------------------------------------------------------------
// Gather SpMM: one warp per dst node; lane l owns feats 4l..4l+3 (8 fp16 B).
// fp32 accumulation.  Unroll x4 with PLAIN int2 slot loads (R9 form, inferred
// ~31us).  No int4 reinterpret-cast, no cnt reset (R7's poisons).
// ---------------------------------------------------------------------------
__global__ __launch_bounds__(256) void spmm_gather_kernel(
    const int* __restrict__ cnt_arr,
    const int2* __restrict__ slot,
    const __half* __restrict__ hidden,
    float* __restrict__ out)
{
    const int node = blockIdx.x * (blockDim.x >> 5) + (threadIdx.x >> 5);
    const int lane = threadIdx.x & 31;
    if (node >= N_NODES) return;

    int cnt = cnt_arr[node];
    if (cnt > CAP) cnt = CAP;
    const int2* __restrict__ sl = &slot[(size_t)node * CAP];

    float4 acc = make_float4(0.f, 0.f, 0.f, 0.f);

    int j = 0;
    for (; j + 4 <= cnt; j += 4) {
        const int2 e0 = sl[j];
        const int2 e1 = sl[j + 1];
        const int2 e2 = sl[j + 2];
        const int2 e3 = sl[j + 3];
        const uint2 r0 = *(const uint2*)&hidden[(size_t)e0.x * F + lane * 4];
        const uint2 r1 = *(const uint2*)&hidden[(size_t)e1.x * F + lane * 4];
        const uint2 r2 = *(const uint2*)&hidden[(size_t)e2.x * F + lane * 4];
        const uint2 r3 = *(const uint2*)&hidden[(size_t)e3.x * F + lane * 4];
        const float w0 = __int_as_float(e0.y);
        const float w1 = __int_as_float(e1.y);
        const float w2 = __int_as_float(e2.y);
        const float w3 = __int_as_float(e3.y);
        float2 a01, a23;
        a01 = __half22float2(*(const __half2*)&r0.x);
        a23 = __half22float2(*(const __half2*)&r0.y);
        acc.x += w0 * a01.x; acc.y += w0 * a01.y; acc.z += w0 * a23.x; acc.w += w0 * a23.y;
        a01 = __half22float2(*(const __half2*)&r1.x);
        a23 = __half22float2(*(const __half2*)&r1.y);
        acc.x += w1 * a01.x; acc.y += w1 * a01.y; acc.z += w1 * a23.x; acc.w += w1 * a23.y;
        a01 = __half22float2(*(const __half2*)&r2.x);
        a23 = __half22float2(*(const __half2*)&r2.y);
        acc.x += w2 * a01.x; acc.y += w2 * a01.y; acc.z += w2 * a23.x; acc.w += w2 * a23.y;
        a01 = __half22float2(*(const __half2*)&r3.x);
        a23 = __half22float2(*(const __half2*)&r3.y);
        acc.x += w3 * a01.x; acc.y += w3 * a01.y; acc.z += w3 * a23.x; acc.w += w3 * a23.y;
    }
    for (; j + 2 <= cnt; j += 2) {
        const int2 e0 = sl[j];
        const int2 e1 = sl[j + 1];
        const uint2 r0 = *(const uint2*)&hidden[(size_t)e0.x * F + lane * 4];
        const uint2 r1 = *(const uint2*)&hidden[(size_t)e1.x * F + lane * 4];
        const float w0 = __int_as_float(e0.y);
        const float w1 = __int_as_float(e1.y);
        float2 a01, a23;
        a01 = __half22float2(*(const __half2*)&r0.x);
        a23 = __half22float2(*(const __half2*)&r0.y);
        acc.x += w0 * a01.x; acc.y += w0 * a01.y; acc.z += w0 * a23.x; acc.w += w0 * a23.y;
        a01 = __half22float2(*(const __half2*)&r1.x);
        a23 = __half22float2(*(const __half2*)&r1.y);
        acc.x += w1 * a01.x; acc.y += w1 * a01.y; acc.z += w1 * a23.x; acc.w += w1 * a23.y;
    }
    if (j < cnt) {
        const int2 e0 = sl[j];
        const uint2 r0 = *(const uint2*)&hidden[(size_t)e0.x * F + lane * 4];
        const float w0 = __int_as_float(e0.y);
        float2 a01 = __half22float2(*(const __half2*)&r0.x);
        float2 a23 = __half22float2(*(const __half2*)&r0.y);
        acc.x += w0 * a01.x; acc.y += w0 * a01.y; acc.z += w0 * a23.x; acc.w += w0 * a23.y;
    }
    *(float4*)&out[(size_t)node * F + lane * 4] = acc;
}

// ---------------------------------------------------------------------------
// Launch
// Inputs: x [N,128] f32, edge_index [2,E] i32, edge_weight [E] f32,
//         W [128,128] f32, b [128] f32.  Output: [N,128] f32.
// ---------------------------------------------------------------------------
extern "C" void kernel_launch(void* const* d_in, const int* in_sizes, int n_in,
                              void* d_out, int out_size) {
    const float* x  = (const float*)d_in[0];
    const int*   ei = (const int*)d_in[1];
    const float* ew = (const float*)d_in[2];
    const float* W  = (const float*)d_in[3];
    const float* b  = (const float*)d_in[4];
    float* out = (float*)d_out;

    __half* hidden; int* cnt; int2* slot;
    cudaGetSymbolAddress((void**)&hidden, g_hidden);
    cudaGetSymbolAddress((void**)&cnt, g_cnt);
    cudaGetSymbolAddress((void**)&slot, g_slot);

    // A) zero per-dst counters
    {
        const int n4 = (N_NODES + 3) / 4;
        zero_cnt_kernel<<<(n4 + 255) / 256, 256>>>(cnt);
    }
    // B) HMMA GEMM (fp16 hidden, 48KB smem) overlapped with edge bucketing
    gemm_fill_fused_kernel<<<TOTAL_BLOCKS, 256>>>(x, W, b, ei, ew, hidden, cnt, slot);

    // C) out[dst] = sum w * hidden[src]  (gather; writes all rows)
    {
        const int warps_per_block = 256 / 32;
        const int grid = (N_NODES + warps_per_block - 1) / warps_per_block;
        spmm_gather_kernel<<<grid, 256>>>(cnt, slot, hidden, out);
    }
}